// round 1
// baseline (speedup 1.0000x reference)
#include <cuda_runtime.h>
#include <cuda_bf16.h>

#define NLEV 256
#define REP  32   // replicate codebook per bank -> conflict-free LDS

__global__ void __launch_bounds__(256, 6)
agc_quant_kernel(const float4* __restrict__ in4,
                 const float4* __restrict__ mn4,
                 const float*  __restrict__ uvals,
                 float* __restrict__ out_dq,   // d_out[0 .. n)
                 float* __restrict__ out_sym,  // d_out[n .. 2n)  (float-encoded ints)
                 int n4, int n)
{
    __shared__ float us[NLEV * REP];  // 32 KB, us[idx*32 + lane]

    const int tid  = threadIdx.x;
    const int lane = tid & 31;

    // Cooperative fill: consecutive addresses per warp -> conflict-free STS,
    // broadcast LDG (i>>5 identical across a warp's 32-wide run? i consecutive
    // -> i>>5 spans at most 2 values -> at most 2 lines; codebook is L1-hot).
    for (int i = tid; i < NLEV * REP; i += blockDim.x)
        us[i] = uvals[i >> 5];
    __syncthreads();

    const int stride = gridDim.x * blockDim.x;

    for (int i = blockIdx.x * blockDim.x + tid; i < n4; i += stride) {
        float4 x = in4[i];
        float4 m = mn4[i];

        float v[4];
        v[0] = x.x - m.x; v[1] = x.y - m.y; v[2] = x.z - m.z; v[3] = x.w - m.w;

        // Branchless searchsorted-left over 256 sorted values:
        // pos = #{ u < v }  in [0, 256].  4 independent searches interleaved
        // for ILP (hides 29-cyc LDS latency).
        int pos[4] = {0, 0, 0, 0};
        #pragma unroll
        for (int s = 128; s >= 1; s >>= 1) {
            #pragma unroll
            for (int j = 0; j < 4; j++) {
                float probe = us[((pos[j] + s - 1) << 5) + lane];
                if (probe < v[j]) pos[j] += s;
            }
        }

        float dq[4], sy[4];
        #pragma unroll
        for (int j = 0; j < 4; j++) {
            int idx = pos[j];
            idx = idx < 1 ? 1 : (idx > NLEV - 1 ? NLEV - 1 : idx);
            float left  = us[((idx - 1) << 5) + lane];
            float right = us[(idx << 5) + lane];
            bool takeLeft = fabsf(v[j] - left) <= fabsf(v[j] - right);
            int sym = takeLeft ? (idx - 1) : idx;
            float val = takeLeft ? left : right;
            sy[j] = (float)sym;
            dq[j] = val;
        }
        dq[0] += m.x; dq[1] += m.y; dq[2] += m.z; dq[3] += m.w;

        reinterpret_cast<float4*>(out_dq)[i]  = make_float4(dq[0], dq[1], dq[2], dq[3]);
        reinterpret_cast<float4*>(out_sym)[i] = make_float4(sy[0], sy[1], sy[2], sy[3]);
    }

    // Scalar tail (n not divisible by 4) — handled by block 0 only.
    if (blockIdx.x == 0) {
        const float* in1 = reinterpret_cast<const float*>(in4);
        const float* mn1 = reinterpret_cast<const float*>(mn4);
        for (int i = n4 * 4 + tid; i < n; i += blockDim.x) {
            float vv = in1[i] - mn1[i];
            int p = 0;
            #pragma unroll
            for (int s = 128; s >= 1; s >>= 1) {
                float probe = us[((p + s - 1) << 5) + lane];
                if (probe < vv) p += s;
            }
            int idx = p < 1 ? 1 : (p > NLEV - 1 ? NLEV - 1 : p);
            float left  = us[((idx - 1) << 5) + lane];
            float right = us[(idx << 5) + lane];
            bool takeLeft = fabsf(vv - left) <= fabsf(vv - right);
            out_sym[i] = (float)(takeLeft ? (idx - 1) : idx);
            out_dq[i]  = (takeLeft ? left : right) + mn1[i];
        }
    }
}

extern "C" void kernel_launch(void* const* d_in, const int* in_sizes, int n_in,
                              void* d_out, int out_size)
{
    const float* inputs = (const float*)d_in[0];
    const float* means  = (const float*)d_in[1];
    const float* uvals  = (const float*)d_in[2];
    float* out = (float*)d_out;

    const int n  = out_size / 2;          // dequant half + symbols half
    const int n4 = n / 4;

    float* out_dq  = out;
    float* out_sym = out + n;

    // ~6 CTAs/SM on 148 SMs; grid-stride loop amortizes the 32 KB smem fill.
    const int threads = 256;
    int blocks = 888;
    int maxb = (n4 + threads - 1) / threads;
    if (blocks > maxb && maxb > 0) blocks = maxb;
    if (blocks < 1) blocks = 1;

    agc_quant_kernel<<<blocks, threads>>>(
        (const float4*)inputs, (const float4*)means, uvals,
        out_dq, out_sym, n4, n);
}